// round 1
// baseline (speedup 1.0000x reference)
#include <cuda_runtime.h>
#include <math.h>

#define SEQ   4096
#define DIM   1024
#define NHEAD 16
#define HDIM  64
#define FHN   4
#define FDIM  256
#define CSZ   1024
#define NCH   4
#define BASE_LR_INV -6.90725517f

// ------------------------- scratch (static device globals) -------------------------
__device__ float g_qkv[SEQ * 3 * DIM];
__device__ float g_qr[SEQ * DIM];
__device__ float g_kr[SEQ * DIM];
__device__ float g_fq[SEQ * DIM];
__device__ float g_fk[SEQ * DIM];
__device__ float g_fv[SEQ * DIM];
__device__ float g_lrbuf[SEQ * 12];
__device__ float g_ttt[SEQ * DIM];
__device__ float g_ao[SEQ * DIM];
__device__ float g_W0[FHN * FDIM * FDIM];
__device__ float g_W1[FHN * FDIM * FDIM];
__device__ float g_W2[FHN * FDIM * FDIM];
__device__ float g_gk[FHN * CSZ * FDIM];
__device__ float g_hk[FHN * CSZ * FDIM];
__device__ float g_qg[FHN * CSZ * FDIM];
__device__ float g_qm[FHN * CSZ * FDIM];
__device__ float g_dh[FHN * CSZ * FDIM];
__device__ float g_hq[FHN * CSZ * FDIM];
__device__ float g_hid[FHN * CSZ * FDIM];
__device__ float g_dgk[FHN * CSZ * FDIM];
__device__ float g_dhk[FHN * CSZ * FDIM];
__device__ float g_vl1[FHN * CSZ * FDIM];

// ------------------------- generic 64x64 tiled fp32 GEMM body -------------------------
// C[m0:m0+64, n0:n0+64] (+)= op(A) * op(B)
// !transA: A is [M,K] lda ; transA: A is [K,M] lda
// transB:  B is [N,K] ldb ; !transB: B is [K,N] ldb
// Requires: K % 16 == 0, tiles fully in-bounds, 256 threads.
__device__ __forceinline__ void gemm_tile(
    const float* __restrict__ A, const float* __restrict__ B, float* __restrict__ C,
    int m0, int n0, int K, int lda, int ldb, int ldc,
    bool transA, bool transB, bool accum)
{
    __shared__ float As[16][68];
    __shared__ float Bs[16][68];
    const int tid = threadIdx.x;
    const int tx = tid & 15, ty = tid >> 4;
    float acc[4][4] = {};

    for (int k0 = 0; k0 < K; k0 += 16) {
        const int lin = tid * 4;
        if (!transA) {
            int m = lin >> 4, k = lin & 15;
            float4 v = *(const float4*)(A + (long)(m0 + m) * lda + (k0 + k));
            As[k + 0][m] = v.x; As[k + 1][m] = v.y; As[k + 2][m] = v.z; As[k + 3][m] = v.w;
        } else {
            int m = lin & 63, k = lin >> 6;
            float4 v = *(const float4*)(A + (long)(k0 + k) * lda + (m0 + m));
            *(float4*)&As[k][m] = v;
        }
        if (transB) {
            int n = lin >> 4, k = lin & 15;
            float4 v = *(const float4*)(B + (long)(n0 + n) * ldb + (k0 + k));
            Bs[k + 0][n] = v.x; Bs[k + 1][n] = v.y; Bs[k + 2][n] = v.z; Bs[k + 3][n] = v.w;
        } else {
            int n = lin & 63, k = lin >> 6;
            float4 v = *(const float4*)(B + (long)(k0 + k) * ldb + (n0 + n));
            *(float4*)&Bs[k][n] = v;
        }
        __syncthreads();
#pragma unroll
        for (int kk = 0; kk < 16; kk++) {
            float4 a4 = *(const float4*)&As[kk][ty * 4];
            float4 b4 = *(const float4*)&Bs[kk][tx * 4];
            float av[4] = {a4.x, a4.y, a4.z, a4.w};
            float bv[4] = {b4.x, b4.y, b4.z, b4.w};
#pragma unroll
            for (int i = 0; i < 4; i++)
#pragma unroll
                for (int j = 0; j < 4; j++) acc[i][j] += av[i] * bv[j];
        }
        __syncthreads();
    }
#pragma unroll
    for (int i = 0; i < 4; i++) {
        float* cp = C + (long)(m0 + ty * 4 + i) * ldc + n0 + tx * 4;
        if (accum) {
            cp[0] += acc[i][0]; cp[1] += acc[i][1]; cp[2] += acc[i][2]; cp[3] += acc[i][3];
        } else {
            float4 v = {acc[i][0], acc[i][1], acc[i][2], acc[i][3]};
            *(float4*)cp = v;
        }
    }
}

// ------------------------- helpers -------------------------
__device__ __forceinline__ float block_reduce256(float v, float* s_red)
{
    int t = threadIdx.x;
    s_red[t] = v;
    __syncthreads();
#pragma unroll
    for (int o = 128; o > 0; o >>= 1) {
        if (t < o) s_red[t] += s_red[t + o];
        __syncthreads();
    }
    float r = s_red[0];
    __syncthreads();
    return r;
}

__device__ __forceinline__ float sigmoidf_(float x) { return 1.0f / (1.0f + expf(-x)); }

// ------------------------- kernels -------------------------
__global__ void k_initW(const float* __restrict__ w0, const float* __restrict__ w1,
                        const float* __restrict__ w2)
{
    int i = blockIdx.x * blockDim.x + threadIdx.x;
    if (i < FHN * FDIM * FDIM) { g_W0[i] = w0[i]; g_W1[i] = w1[i]; g_W2[i] = w2[i]; }
}

__global__ __launch_bounds__(256) void k_gemm_qkv(const float* __restrict__ x,
                                                  const float* __restrict__ Wqkv)
{
    gemm_tile(x, Wqkv, g_qkv, blockIdx.y * 64, blockIdx.x * 64,
              DIM, DIM, DIM, 3 * DIM, false, true, false);
}

__global__ __launch_bounds__(128) void k_lr(const float* __restrict__ x,
                                            const float* __restrict__ Wlr,
                                            const float* __restrict__ blr)
{
    __shared__ float sx[DIM];
    int s = blockIdx.x;
    for (int i = threadIdx.x; i < DIM; i += 128) sx[i] = x[(long)s * DIM + i];
    __syncthreads();
    int w = threadIdx.x >> 5, lane = threadIdx.x & 31;
    for (int j = w; j < 12; j += 4) {
        float sum = 0.0f;
        for (int d = lane; d < DIM; d += 32) sum += sx[d] * Wlr[(long)j * DIM + d];
#pragma unroll
        for (int o = 16; o > 0; o >>= 1) sum += __shfl_xor_sync(0xffffffffu, sum, o);
        if (lane == 0) {
            float v = sum + blr[j] + BASE_LR_INV;
            g_lrbuf[s * 12 + j] = (v > 20.0f) ? v : log1pf(expf(v));
        }
    }
}

// RMSNorm(q,k) + fast-weight inputs (silu/scale/l2norm) + fv + RoPE(q,k)
__global__ __launch_bounds__(256) void k_post(const float* __restrict__ qnw,
                                              const float* __restrict__ knw,
                                              const float* __restrict__ qks,
                                              const float* __restrict__ qko)
{
    __shared__ float s_q[DIM];
    __shared__ float s_k[DIM];
    __shared__ float s_red[256];
    __shared__ float s_cs[32], s_sn[32];

    int s = blockIdx.x, t = threadIdx.x;
    const float* qrow = g_qkv + (long)s * 3072;
    const float* krow = qrow + DIM;
    const float* vrow = qrow + 2 * DIM;

    if (t < 32) {  // RoPE table for this position (fp64 angle + range reduction)
        double inv = exp(-((double)(2 * t) / 64.0) * log(500000.0));
        double a = (double)s * inv;
        const double tw = 6.283185307179586476925286766559;
        a -= floor(a / tw) * tw;
        s_cs[t] = (float)cos(a);
        s_sn[t] = (float)sin(a);
    }

    float qv[4], kv[4], vv[4];
    float sq = 0.0f, sk = 0.0f;
#pragma unroll
    for (int i = 0; i < 4; i++) {
        int d = t + 256 * i;
        qv[i] = qrow[d]; kv[i] = krow[d]; vv[i] = vrow[d];
        sq += qv[i] * qv[i]; sk += kv[i] * kv[i];
    }
    float tq = block_reduce256(sq, s_red);
    float tk = block_reduce256(sk, s_red);
    float rq = rsqrtf(tq / 1024.0f + 1e-5f);
    float rk = rsqrtf(tk / 1024.0f + 1e-5f);

    float fqv[4], fkv[4];
#pragma unroll
    for (int i = 0; i < 4; i++) {
        int d = t + 256 * i;
        float qn = qv[i] * rq * qnw[d];
        float kn = kv[i] * rk * knw[d];
        s_q[d] = qn; s_k[d] = kn;
        fqv[i] = qn * sigmoidf_(qn) * qks[2 * d + 0] + qko[2 * d + 0];
        fkv[i] = kn * sigmoidf_(kn) * qks[2 * d + 1] + qko[2 * d + 1];
        g_fv[(long)s * DIM + d] = vv[i] * sigmoidf_(vv[i]);
    }
    // per-fw-head l2 norms (head index == i for this thread mapping)
    float rfq[4], rfk[4];
#pragma unroll
    for (int i = 0; i < 4; i++) {
        float hs = block_reduce256(fqv[i] * fqv[i], s_red);
        rfq[i] = rsqrtf(hs + 1e-6f);
        hs = block_reduce256(fkv[i] * fkv[i], s_red);
        rfk[i] = rsqrtf(hs + 1e-6f);
    }
#pragma unroll
    for (int i = 0; i < 4; i++) {
        int d = t + 256 * i;
        g_fq[(long)s * DIM + d] = fqv[i] * rfq[i];
        g_fk[(long)s * DIM + d] = fkv[i] * rfk[i];
    }
    __syncthreads();  // s_q/s_k + rope table visible
#pragma unroll
    for (int i = 0; i < 4; i++) {
        int d = t + 256 * i;
        int r = d & 63, ip = r & 31;
        float c = s_cs[ip], sn = s_sn[ip];
        float x1q = s_q[d], xpq = s_q[d ^ 32];
        float x1k = s_k[d], xpk = s_k[d ^ 32];
        g_qr[(long)s * DIM + d] = (r < 32) ? x1q * c - xpq * sn : x1q * c + xpq * sn;
        g_kr[(long)s * DIM + d] = (r < 32) ? x1k * c - xpk * sn : x1k * c + xpk * sn;
    }
}

// TTT stage 1: gk,hk,qg,qm (A@W^T) and dh (A@W1), batched over (head, op)
__global__ __launch_bounds__(256) void k_ttt1(int c)
{
    int z = blockIdx.z;
    int h = z / 5, op = z - h * 5;
    long choff = (long)c * CSZ * DIM + h * FDIM;
    const float* A; const float* B; float* Cp; bool tb = true;
    switch (op) {
        case 0: A = g_fk + choff; B = g_W0 + h * FDIM * FDIM; Cp = g_gk + (long)h * CSZ * FDIM; break;
        case 1: A = g_fk + choff; B = g_W2 + h * FDIM * FDIM; Cp = g_hk + (long)h * CSZ * FDIM; break;
        case 2: A = g_fq + choff; B = g_W0 + h * FDIM * FDIM; Cp = g_qg + (long)h * CSZ * FDIM; break;
        case 3: A = g_fq + choff; B = g_W2 + h * FDIM * FDIM; Cp = g_qm + (long)h * CSZ * FDIM; break;
        default: A = g_fv + choff; B = g_W1 + h * FDIM * FDIM; Cp = g_dh + (long)h * CSZ * FDIM; tb = false; break;
    }
    gemm_tile(A, B, Cp, blockIdx.y * 64, blockIdx.x * 64, FDIM, DIM, FDIM, FDIM, false, tb, false);
}

// TTT stage 2: elementwise activations / lr scaling
__global__ __launch_bounds__(256) void k_ttt2(int c)
{
    long idx = (long)blockIdx.x * 256 + threadIdx.x;  // < FHN*CSZ*FDIM = 2^20
    int h = (int)(idx >> 18);
    int rem = (int)(idx & 262143);
    int t = rem >> 8;
    int e = rem & 255;
    int sg = c * CSZ + t;
    float l0 = g_lrbuf[sg * 12 + h];
    float l1 = g_lrbuf[sg * 12 + 4 + h];
    float l2 = g_lrbuf[sg * 12 + 8 + h];
    float gk = g_gk[idx], hk = g_hk[idx], dh = g_dh[idx];
    float qg = g_qg[idx], qm = g_qm[idx];
    float sgm = sigmoidf_(gk);
    float sil = gk * sgm;
    g_hq[idx]  = qg * sigmoidf_(qg) * qm;
    g_hid[idx] = sil * hk;
    float dsil = sgm * (1.0f + gk * (1.0f - sgm));
    g_dgk[idx] = dh * hk * dsil * l0;
    g_dhk[idx] = dh * sil * l2;
    g_vl1[idx] = g_fv[(long)sg * DIM + h * FDIM + e] * l1;
}

// TTT stage 3: oi = hq @ W1^T  (uses pre-update W1)
__global__ __launch_bounds__(256) void k_ttt3(int c)
{
    int h = blockIdx.z;
    gemm_tile(g_hq + (long)h * CSZ * FDIM, g_W1 + h * FDIM * FDIM,
              g_ttt + (long)c * CSZ * DIM + h * FDIM,
              blockIdx.y * 64, blockIdx.x * 64, FDIM, FDIM, FDIM, DIM, false, true, false);
}

// TTT stage 4: rank-CSZ weight updates (A^T @ B accumulate), batched over (head, op)
__global__ __launch_bounds__(256) void k_ttt4(int c)
{
    int z = blockIdx.z;
    int h = z / 3, op = z - h * 3;
    long koff = (long)c * CSZ * DIM + h * FDIM;
    const float* A; const float* B; float* Cp; int ldb;
    switch (op) {
        case 0: A = g_vl1 + (long)h * CSZ * FDIM; B = g_hid + (long)h * CSZ * FDIM;
                Cp = g_W1 + h * FDIM * FDIM; ldb = FDIM; break;
        case 1: A = g_dgk + (long)h * CSZ * FDIM; B = g_fk + koff;
                Cp = g_W0 + h * FDIM * FDIM; ldb = DIM; break;
        default: A = g_dhk + (long)h * CSZ * FDIM; B = g_fk + koff;
                Cp = g_W2 + h * FDIM * FDIM; ldb = DIM; break;
    }
    gemm_tile(A, B, Cp, blockIdx.y * 64, blockIdx.x * 64, CSZ, FDIM, ldb, FDIM, true, false, true);
}

// Sliding-window (1024 incl self) flash attention, fp32, 64-query tiles
__global__ __launch_bounds__(256) void k_attn()
{
    __shared__ float sQt[64][64];  // Q^T  [d][q]
    __shared__ float sKP[64][64];  // K^T [d][kj], then reused as P^T [kj][q]
    __shared__ float sV[64][64];   // V   [kj][d]
    int h = blockIdx.y, qt = blockIdx.x;
    int p0 = qt * 64;
    int tid = threadIdx.x;
    int tx = tid & 15, ty = tid >> 4;

    for (int l = tid; l < 1024; l += 256) {
        int r = l >> 4, c4 = (l & 15) << 2;
        float4 v = *(const float4*)&g_qr[(long)(p0 + r) * DIM + h * HDIM + c4];
        sQt[c4 + 0][r] = v.x; sQt[c4 + 1][r] = v.y; sQt[c4 + 2][r] = v.z; sQt[c4 + 3][r] = v.w;
    }

    float m[4], lsum[4], O[4][4];
#pragma unroll
    for (int i = 0; i < 4; i++) {
        m[i] = -1e30f; lsum[i] = 0.0f;
#pragma unroll
        for (int j = 0; j < 4; j++) O[i][j] = 0.0f;
    }

    int ktlo = (qt >= 16) ? qt - 16 : 0;
    for (int kt = ktlo; kt <= qt; kt++) {
        __syncthreads();
        for (int l = tid; l < 1024; l += 256) {
            int r = l >> 4, c4 = (l & 15) << 2;
            float4 kv = *(const float4*)&g_kr[(long)(kt * 64 + r) * DIM + h * HDIM + c4];
            sKP[c4 + 0][r] = kv.x; sKP[c4 + 1][r] = kv.y; sKP[c4 + 2][r] = kv.z; sKP[c4 + 3][r] = kv.w;
            float4 vv = *(const float4*)&g_qkv[(long)(kt * 64 + r) * 3072 + 2048 + h * HDIM + c4];
            *(float4*)&sV[r][c4] = vv;
        }
        __syncthreads();

        float sc[4][4] = {};
#pragma unroll 8
        for (int kk = 0; kk < 64; kk++) {
            float4 a4 = *(const float4*)&sQt[kk][ty << 2];
            float4 b4 = *(const float4*)&sKP[kk][tx << 2];
            float av[4] = {a4.x, a4.y, a4.z, a4.w};
            float bv[4] = {b4.x, b4.y, b4.z, b4.w};
#pragma unroll
            for (int i = 0; i < 4; i++)
#pragma unroll
                for (int j = 0; j < 4; j++) sc[i][j] += av[i] * bv[j];
        }
#pragma unroll
        for (int i = 0; i < 4; i++) {
            int p = p0 + ty * 4 + i;
#pragma unroll
            for (int j = 0; j < 4; j++) {
                int g = kt * 64 + tx * 4 + j;
                sc[i][j] = (g > p - 1024 && g <= p) ? sc[i][j] * 0.125f : -1e30f;
            }
        }
        float pm[4][4];
#pragma unroll
        for (int i = 0; i < 4; i++) {
            float tm = fmaxf(fmaxf(sc[i][0], sc[i][1]), fmaxf(sc[i][2], sc[i][3]));
#pragma unroll
            for (int o = 1; o < 16; o <<= 1) tm = fmaxf(tm, __shfl_xor_sync(0xffffffffu, tm, o));
            float mn = fmaxf(m[i], tm);
            float alpha = expf(m[i] - mn);
            float rs = 0.0f;
#pragma unroll
            for (int j = 0; j < 4; j++) { pm[i][j] = expf(sc[i][j] - mn); rs += pm[i][j]; }
#pragma unroll
            for (int o = 1; o < 16; o <<= 1) rs += __shfl_xor_sync(0xffffffffu, rs, o);
            lsum[i] = lsum[i] * alpha + rs;
            m[i] = mn;
#pragma unroll
            for (int j = 0; j < 4; j++) O[i][j] *= alpha;
        }
        __syncthreads();  // done reading sKP as K^T
#pragma unroll
        for (int i = 0; i < 4; i++)
#pragma unroll
            for (int j = 0; j < 4; j++) sKP[tx * 4 + j][ty * 4 + i] = pm[i][j];
        __syncthreads();
#pragma unroll 8
        for (int kk = 0; kk < 64; kk++) {
            float4 a4 = *(const float4*)&sKP[kk][ty << 2];
            float4 b4 = *(const float4*)&sV[kk][tx << 2];
            float av[4] = {a4.x, a4.y, a4.z, a4.w};
            float bv[4] = {b4.x, b4.y, b4.z, b4.w};
#pragma unroll
            for (int i = 0; i < 4; i++)
#pragma unroll
                for (int j = 0; j < 4; j++) O[i][j] += av[i] * bv[j];
        }
    }
#pragma unroll
    for (int i = 0; i < 4; i++) {
        float inv = 1.0f / lsum[i];
#pragma unroll
        for (int j = 0; j < 4; j++)
            g_ao[(long)(p0 + ty * 4 + i) * DIM + h * HDIM + tx * 4 + j] = O[i][j] * inv;
    }
}

// TTT rmsnorm + add into g_ao
__global__ __launch_bounds__(256) void k_comb(const float* __restrict__ tnw)
{
    __shared__ float s_red[256];
    int s = blockIdx.x, t = threadIdx.x;
    float v[4], r[4];
#pragma unroll
    for (int i = 0; i < 4; i++) v[i] = g_ttt[(long)s * DIM + t + 256 * i];
#pragma unroll
    for (int i = 0; i < 4; i++) {
        float tot = block_reduce256(v[i] * v[i], s_red);
        r[i] = rsqrtf(tot / 256.0f + 1e-5f);
    }
    float w = tnw[t];
#pragma unroll
    for (int i = 0; i < 4; i++) g_ao[(long)s * DIM + t + 256 * i] += v[i] * r[i] * w;
}

__global__ __launch_bounds__(256) void k_gemm_out(const float* __restrict__ Wo,
                                                 float* __restrict__ out)
{
    gemm_tile(g_ao, Wo, out, blockIdx.y * 64, blockIdx.x * 64,
              DIM, DIM, DIM, DIM, false, true, false);
}

// ------------------------- launch -------------------------
extern "C" void kernel_launch(void* const* d_in, const int* in_sizes, int n_in,
                              void* d_out, int out_size)
{
    const float* x    = (const float*)d_in[0];
    const float* Wqkv = (const float*)d_in[1];
    const float* qnw  = (const float*)d_in[2];
    const float* knw  = (const float*)d_in[3];
    const float* Wo   = (const float*)d_in[4];
    const float* w0   = (const float*)d_in[5];
    const float* w1   = (const float*)d_in[6];
    const float* w2   = (const float*)d_in[7];
    const float* Wlr  = (const float*)d_in[8];
    const float* blr  = (const float*)d_in[9];
    const float* qks  = (const float*)d_in[10];
    const float* qko  = (const float*)d_in[11];
    const float* tnw  = (const float*)d_in[12];
    float* out = (float*)d_out;

    k_initW<<<1024, 256>>>(w0, w1, w2);
    k_gemm_qkv<<<dim3(48, 64), 256>>>(x, Wqkv);
    k_lr<<<4096, 128>>>(x, Wlr, blr);
    k_post<<<4096, 256>>>(qnw, knw, qks, qko);

    for (int c = 0; c < NCH; c++) {
        k_ttt1<<<dim3(4, 16, 20), 256>>>(c);
        k_ttt2<<<4096, 256>>>(c);
        k_ttt3<<<dim3(4, 16, 4), 256>>>(c);
        k_ttt4<<<dim3(4, 4, 12), 256>>>(c);
    }

    k_attn<<<dim3(64, 16), 256>>>();
    k_comb<<<4096, 256>>>(tnw);
    k_gemm_out<<<dim3(16, 64), 256>>>(Wo, out);
}

// round 2
// speedup vs baseline: 1.8935x; 1.8935x over previous
#include <cuda_runtime.h>
#include <math.h>

#define SEQ   4096
#define DIM   1024
#define NHEAD 16
#define HDIM  64
#define FHN   4
#define FDIM  256
#define CSZ   1024
#define NCH   4
#define BASE_LR_INV -6.90725517f

// ------------------------- scratch (static device globals) -------------------------
__device__ float g_qkv[SEQ * 3 * DIM];
__device__ float g_qr[SEQ * DIM];
__device__ float g_kr[SEQ * DIM];
__device__ float g_fq[SEQ * DIM];
__device__ float g_fk[SEQ * DIM];
__device__ float g_fv[SEQ * DIM];
__device__ float g_lrbuf[SEQ * 12];
__device__ float g_ttt[SEQ * DIM];
__device__ float g_ao[SEQ * DIM];
__device__ float g_W0[FHN * FDIM * FDIM];
__device__ float g_W1[FHN * FDIM * FDIM];
__device__ float g_W2[FHN * FDIM * FDIM];
__device__ float g_gk[FHN * CSZ * FDIM];
__device__ float g_hk[FHN * CSZ * FDIM];
__device__ float g_qg[FHN * CSZ * FDIM];
__device__ float g_qm[FHN * CSZ * FDIM];
__device__ float g_dh[FHN * CSZ * FDIM];
__device__ float g_hq[FHN * CSZ * FDIM];
__device__ float g_hid[FHN * CSZ * FDIM];
__device__ float g_dgk[FHN * CSZ * FDIM];
__device__ float g_dhk[FHN * CSZ * FDIM];
__device__ float g_vl1[FHN * CSZ * FDIM];

// ------------------------- tf32 mma primitives -------------------------
__device__ __forceinline__ unsigned f2tf(float f)
{
    unsigned u;
    asm("cvt.rna.tf32.f32 %0, %1;" : "=r"(u) : "f"(f));
    return u;
}

__device__ __forceinline__ void mma8(float* c, const unsigned* a, const unsigned* b)
{
    asm volatile(
        "mma.sync.aligned.m16n8k8.row.col.f32.tf32.tf32.f32 "
        "{%0,%1,%2,%3},{%4,%5,%6,%7},{%8,%9},{%0,%1,%2,%3};"
        : "+f"(c[0]), "+f"(c[1]), "+f"(c[2]), "+f"(c[3])
        : "r"(a[0]), "r"(a[1]), "r"(a[2]), "r"(a[3]), "r"(b[0]), "r"(b[1]));
}

// ------------------------- generic tf32 GEMM, CTA tile 128x64, K%16==0 ----------
// !transA: A is [M,K] lda ; transA: A is [K,M] lda
// transB:  B is [N,K] ldb ; !transB: B is [K,N] ldb
__device__ __forceinline__ void gemm_tf32(
    const float* __restrict__ A, const float* __restrict__ B, float* __restrict__ C,
    int m0, int n0, int K, int lda, int ldb, int ldc,
    bool transA, bool transB, bool accum)
{
    __shared__ float As[16][136];  // [k][m], stride%32==8 -> conflict-free frag loads
    __shared__ float Bs[16][72];   // [k][n]
    const int tid = threadIdx.x;
    const int lane = tid & 31, warp = tid >> 5;
    const int wm = warp >> 1, wn = warp & 1;
    const int gid = lane >> 2, tig = lane & 3;

    float acc[2][4][4];
#pragma unroll
    for (int i = 0; i < 2; i++)
#pragma unroll
        for (int j = 0; j < 4; j++)
#pragma unroll
            for (int l = 0; l < 4; l++) acc[i][j][l] = 0.0f;

    for (int k0 = 0; k0 < K; k0 += 16) {
        if (!transA) {
#pragma unroll
            for (int s = 0; s < 2; s++) {
                int lin = tid + 256 * s;
                int m = lin >> 2, kq = (lin & 3) * 4;
                float4 v = *(const float4*)(A + (long)(m0 + m) * lda + (k0 + kq));
                As[kq + 0][m] = v.x; As[kq + 1][m] = v.y;
                As[kq + 2][m] = v.z; As[kq + 3][m] = v.w;
            }
        } else {
#pragma unroll
            for (int s = 0; s < 2; s++) {
                int lin = tid + 256 * s;
                int k = lin >> 5, m4 = (lin & 31) * 4;
                float4 v = *(const float4*)(A + (long)(k0 + k) * lda + (m0 + m4));
                *(float4*)&As[k][m4] = v;
            }
        }
        if (transB) {
            int n = tid >> 2, kq = (tid & 3) * 4;
            float4 v = *(const float4*)(B + (long)(n0 + n) * ldb + (k0 + kq));
            Bs[kq + 0][n] = v.x; Bs[kq + 1][n] = v.y;
            Bs[kq + 2][n] = v.z; Bs[kq + 3][n] = v.w;
        } else {
            int k = tid >> 4, n4 = (tid & 15) * 4;
            float4 v = *(const float4*)(B + (long)(k0 + k) * ldb + (n0 + n4));
            *(float4*)&Bs[k][n4] = v;
        }
        __syncthreads();
#pragma unroll
        for (int kh = 0; kh < 16; kh += 8) {
            unsigned a[2][4], b[4][2];
#pragma unroll
            for (int fm = 0; fm < 2; fm++) {
                int mb = wm * 32 + fm * 16;
                a[fm][0] = f2tf(As[kh + tig][mb + gid]);
                a[fm][1] = f2tf(As[kh + tig][mb + gid + 8]);
                a[fm][2] = f2tf(As[kh + tig + 4][mb + gid]);
                a[fm][3] = f2tf(As[kh + tig + 4][mb + gid + 8]);
            }
#pragma unroll
            for (int fn = 0; fn < 4; fn++) {
                int nb = wn * 32 + fn * 8;
                b[fn][0] = f2tf(Bs[kh + tig][nb + gid]);
                b[fn][1] = f2tf(Bs[kh + tig + 4][nb + gid]);
            }
#pragma unroll
            for (int fm = 0; fm < 2; fm++)
#pragma unroll
                for (int fn = 0; fn < 4; fn++) mma8(acc[fm][fn], a[fm], b[fn]);
        }
        __syncthreads();
    }
#pragma unroll
    for (int fm = 0; fm < 2; fm++) {
        int r0 = m0 + wm * 32 + fm * 16 + gid;
#pragma unroll
        for (int fn = 0; fn < 4; fn++) {
            int cc = n0 + wn * 32 + fn * 8 + 2 * tig;
            float* p0 = C + (long)r0 * ldc + cc;
            float* p1 = C + (long)(r0 + 8) * ldc + cc;
            if (accum) {
                p0[0] += acc[fm][fn][0]; p0[1] += acc[fm][fn][1];
                p1[0] += acc[fm][fn][2]; p1[1] += acc[fm][fn][3];
            } else {
                p0[0] = acc[fm][fn][0]; p0[1] = acc[fm][fn][1];
                p1[0] = acc[fm][fn][2]; p1[1] = acc[fm][fn][3];
            }
        }
    }
}

// ------------------------- helpers -------------------------
__device__ __forceinline__ float block_reduce256(float v, float* s_red)
{
    int t = threadIdx.x;
    s_red[t] = v;
    __syncthreads();
#pragma unroll
    for (int o = 128; o > 0; o >>= 1) {
        if (t < o) s_red[t] += s_red[t + o];
        __syncthreads();
    }
    float r = s_red[0];
    __syncthreads();
    return r;
}

__device__ __forceinline__ float sigmoidf_(float x) { return 1.0f / (1.0f + expf(-x)); }

// ------------------------- kernels -------------------------
__global__ void k_initW(const float* __restrict__ w0, const float* __restrict__ w1,
                        const float* __restrict__ w2)
{
    int i = blockIdx.x * blockDim.x + threadIdx.x;
    if (i < FHN * FDIM * FDIM) { g_W0[i] = w0[i]; g_W1[i] = w1[i]; g_W2[i] = w2[i]; }
}

__global__ __launch_bounds__(256) void k_gemm_qkv(const float* __restrict__ x,
                                                  const float* __restrict__ Wqkv)
{
    gemm_tf32(x, Wqkv, g_qkv, blockIdx.y * 128, blockIdx.x * 64,
              DIM, DIM, DIM, 3 * DIM, false, true, false);
}

__global__ __launch_bounds__(128) void k_lr(const float* __restrict__ x,
                                            const float* __restrict__ Wlr,
                                            const float* __restrict__ blr)
{
    __shared__ float sx[DIM];
    int s = blockIdx.x;
    for (int i = threadIdx.x; i < DIM; i += 128) sx[i] = x[(long)s * DIM + i];
    __syncthreads();
    int w = threadIdx.x >> 5, lane = threadIdx.x & 31;
    for (int j = w; j < 12; j += 4) {
        float sum = 0.0f;
        for (int d = lane; d < DIM; d += 32) sum += sx[d] * Wlr[(long)j * DIM + d];
#pragma unroll
        for (int o = 16; o > 0; o >>= 1) sum += __shfl_xor_sync(0xffffffffu, sum, o);
        if (lane == 0) {
            float v = sum + blr[j] + BASE_LR_INV;
            g_lrbuf[s * 12 + j] = (v > 20.0f) ? v : log1pf(expf(v));
        }
    }
}

// RMSNorm(q,k) + fast-weight inputs (silu/scale/l2norm) + fv + RoPE(q,k)
__global__ __launch_bounds__(256) void k_post(const float* __restrict__ qnw,
                                              const float* __restrict__ knw,
                                              const float* __restrict__ qks,
                                              const float* __restrict__ qko)
{
    __shared__ float s_q[DIM];
    __shared__ float s_k[DIM];
    __shared__ float s_red[256];
    __shared__ float s_cs[32], s_sn[32];

    int s = blockIdx.x, t = threadIdx.x;
    const float* qrow = g_qkv + (long)s * 3072;
    const float* krow = qrow + DIM;
    const float* vrow = qrow + 2 * DIM;

    if (t < 32) {
        double inv = exp(-((double)(2 * t) / 64.0) * log(500000.0));
        double a = (double)s * inv;
        const double tw = 6.283185307179586476925286766559;
        a -= floor(a / tw) * tw;
        s_cs[t] = (float)cos(a);
        s_sn[t] = (float)sin(a);
    }

    float qv[4], kv[4], vv[4];
    float sq = 0.0f, sk = 0.0f;
#pragma unroll
    for (int i = 0; i < 4; i++) {
        int d = t + 256 * i;
        qv[i] = qrow[d]; kv[i] = krow[d]; vv[i] = vrow[d];
        sq += qv[i] * qv[i]; sk += kv[i] * kv[i];
    }
    float tq = block_reduce256(sq, s_red);
    float tk = block_reduce256(sk, s_red);
    float rq = rsqrtf(tq / 1024.0f + 1e-5f);
    float rk = rsqrtf(tk / 1024.0f + 1e-5f);

    float fqv[4], fkv[4];
#pragma unroll
    for (int i = 0; i < 4; i++) {
        int d = t + 256 * i;
        float qn = qv[i] * rq * qnw[d];
        float kn = kv[i] * rk * knw[d];
        s_q[d] = qn; s_k[d] = kn;
        fqv[i] = qn * sigmoidf_(qn) * qks[2 * d + 0] + qko[2 * d + 0];
        fkv[i] = kn * sigmoidf_(kn) * qks[2 * d + 1] + qko[2 * d + 1];
        g_fv[(long)s * DIM + d] = vv[i] * sigmoidf_(vv[i]);
    }
    float rfq[4], rfk[4];
#pragma unroll
    for (int i = 0; i < 4; i++) {
        float hs = block_reduce256(fqv[i] * fqv[i], s_red);
        rfq[i] = rsqrtf(hs + 1e-6f);
        hs = block_reduce256(fkv[i] * fkv[i], s_red);
        rfk[i] = rsqrtf(hs + 1e-6f);
    }
#pragma unroll
    for (int i = 0; i < 4; i++) {
        int d = t + 256 * i;
        g_fq[(long)s * DIM + d] = fqv[i] * rfq[i];
        g_fk[(long)s * DIM + d] = fkv[i] * rfk[i];
    }
    __syncthreads();
#pragma unroll
    for (int i = 0; i < 4; i++) {
        int d = t + 256 * i;
        int r = d & 63, ip = r & 31;
        float c = s_cs[ip], sn = s_sn[ip];
        float x1q = s_q[d], xpq = s_q[d ^ 32];
        float x1k = s_k[d], xpk = s_k[d ^ 32];
        g_qr[(long)s * DIM + d] = (r < 32) ? x1q * c - xpq * sn : x1q * c + xpq * sn;
        g_kr[(long)s * DIM + d] = (r < 32) ? x1k * c - xpk * sn : x1k * c + xpk * sn;
    }
}

// TTT stage 1: gk,hk,qg,qm (A@W^T) and dh (A@W1)
__global__ __launch_bounds__(256) void k_ttt1(int c)
{
    int z = blockIdx.z;
    int h = z / 5, op = z - h * 5;
    long choff = (long)c * CSZ * DIM + h * FDIM;
    const float* A; const float* B; float* Cp; bool tb = true;
    switch (op) {
        case 0: A = g_fk + choff; B = g_W0 + h * FDIM * FDIM; Cp = g_gk + (long)h * CSZ * FDIM; break;
        case 1: A = g_fk + choff; B = g_W2 + h * FDIM * FDIM; Cp = g_hk + (long)h * CSZ * FDIM; break;
        case 2: A = g_fq + choff; B = g_W0 + h * FDIM * FDIM; Cp = g_qg + (long)h * CSZ * FDIM; break;
        case 3: A = g_fq + choff; B = g_W2 + h * FDIM * FDIM; Cp = g_qm + (long)h * CSZ * FDIM; break;
        default: A = g_fv + choff; B = g_W1 + h * FDIM * FDIM; Cp = g_dh + (long)h * CSZ * FDIM; tb = false; break;
    }
    gemm_tf32(A, B, Cp, blockIdx.y * 128, blockIdx.x * 64, FDIM, DIM, FDIM, FDIM, false, tb, false);
}

// TTT stage 2: elementwise activations / lr scaling
__global__ __launch_bounds__(256) void k_ttt2(int c)
{
    long idx = (long)blockIdx.x * 256 + threadIdx.x;
    int h = (int)(idx >> 18);
    int rem = (int)(idx & 262143);
    int t = rem >> 8;
    int e = rem & 255;
    int sg = c * CSZ + t;
    float l0 = g_lrbuf[sg * 12 + h];
    float l1 = g_lrbuf[sg * 12 + 4 + h];
    float l2 = g_lrbuf[sg * 12 + 8 + h];
    float gk = g_gk[idx], hk = g_hk[idx], dh = g_dh[idx];
    float qg = g_qg[idx], qm = g_qm[idx];
    float sgm = sigmoidf_(gk);
    float sil = gk * sgm;
    g_hq[idx]  = qg * sigmoidf_(qg) * qm;
    g_hid[idx] = sil * hk;
    float dsil = sgm * (1.0f + gk * (1.0f - sgm));
    g_dgk[idx] = dh * hk * dsil * l0;
    g_dhk[idx] = dh * sil * l2;
    g_vl1[idx] = g_fv[(long)sg * DIM + h * FDIM + e] * l1;
}

// TTT stage 3: oi = hq @ W1^T
__global__ __launch_bounds__(256) void k_ttt3(int c)
{
    int h = blockIdx.z;
    gemm_tf32(g_hq + (long)h * CSZ * FDIM, g_W1 + h * FDIM * FDIM,
              g_ttt + (long)c * CSZ * DIM + h * FDIM,
              blockIdx.y * 128, blockIdx.x * 64, FDIM, FDIM, FDIM, DIM, false, true, false);
}

// TTT stage 4: rank-CSZ weight updates (A^T @ B accumulate)
__global__ __launch_bounds__(256) void k_ttt4(int c)
{
    int z = blockIdx.z;
    int h = z / 3, op = z - h * 3;
    long koff = (long)c * CSZ * DIM + h * FDIM;
    const float* A; const float* B; float* Cp; int ldb;
    switch (op) {
        case 0: A = g_vl1 + (long)h * CSZ * FDIM; B = g_hid + (long)h * CSZ * FDIM;
                Cp = g_W1 + h * FDIM * FDIM; ldb = FDIM; break;
        case 1: A = g_dgk + (long)h * CSZ * FDIM; B = g_fk + koff;
                Cp = g_W0 + h * FDIM * FDIM; ldb = DIM; break;
        default: A = g_dhk + (long)h * CSZ * FDIM; B = g_fk + koff;
                Cp = g_W2 + h * FDIM * FDIM; ldb = DIM; break;
    }
    gemm_tf32(A, B, Cp, blockIdx.y * 128, blockIdx.x * 64, CSZ, FDIM, ldb, FDIM, true, false, true);
}

// ------------------------- tf32 flash attention, 128-query tiles -------------------------
#define SQSTR 68
#define SKSTR 68
#define SVSTR 72
#define ATTN_SMEM ((128 * SQSTR + 64 * SKSTR + 64 * SVSTR) * 4)

__global__ __launch_bounds__(256) void k_attn()
{
    extern __shared__ float sm[];
    float* sQP = sm;                         // [128][SQSTR] : Q then P
    float* sK  = sm + 128 * SQSTR;           // [64][SKSTR]  : K row=key col=d
    float* sV  = sm + 128 * SQSTR + 64 * SKSTR;  // [64][SVSTR] : V row=key col=d

    const int h = blockIdx.y, qt = blockIdx.x;
    const int p0 = qt * 128;
    const int tid = threadIdx.x;
    const int lane = tid & 31, warp = tid >> 5;
    const int gid = lane >> 2, tig = lane & 3;

    // stage Q (128 x 64)
#pragma unroll
    for (int s = 0; s < 8; s++) {
        int lin = tid + 256 * s;
        int r = lin >> 4, c4 = (lin & 15) * 4;
        *(float4*)&sQP[r * SQSTR + c4] =
            *(const float4*)&g_qr[(long)(p0 + r) * DIM + h * HDIM + c4];
    }
    __syncthreads();

    const int rq = warp * 16 + gid;
    unsigned qa[8][4];
#pragma unroll
    for (int kb = 0; kb < 8; kb++) {
        qa[kb][0] = f2tf(0.125f * sQP[rq * SQSTR + kb * 8 + tig]);
        qa[kb][1] = f2tf(0.125f * sQP[(rq + 8) * SQSTR + kb * 8 + tig]);
        qa[kb][2] = f2tf(0.125f * sQP[rq * SQSTR + kb * 8 + tig + 4]);
        qa[kb][3] = f2tf(0.125f * sQP[(rq + 8) * SQSTR + kb * 8 + tig + 4]);
    }

    float o[8][4];
#pragma unroll
    for (int fn = 0; fn < 8; fn++)
#pragma unroll
        for (int j = 0; j < 4; j++) o[fn][j] = 0.0f;
    float mrow0 = -1e30f, mrow1 = -1e30f, lsum0 = 0.0f, lsum1 = 0.0f;

    const int ktlo = (qt >= 8) ? 2 * qt - 16 : 0;
    const int kthi = 2 * qt + 1;
    const int prow0 = p0 + warp * 16 + gid;
    const int prow1 = prow0 + 8;

    for (int kt = ktlo; kt <= kthi; kt++) {
        __syncthreads();
#pragma unroll
        for (int s = 0; s < 4; s++) {
            int lin = tid + 256 * s;
            int r = lin >> 4, c4 = (lin & 15) * 4;
            *(float4*)&sK[r * SKSTR + c4] =
                *(const float4*)&g_kr[(long)(kt * 64 + r) * DIM + h * HDIM + c4];
            *(float4*)&sV[r * SVSTR + c4] =
                *(const float4*)&g_qkv[(long)(kt * 64 + r) * 3072 + 2048 + h * HDIM + c4];
        }
        __syncthreads();

        float sc[8][4];
#pragma unroll
        for (int fn = 0; fn < 8; fn++)
#pragma unroll
            for (int j = 0; j < 4; j++) sc[fn][j] = 0.0f;

#pragma unroll
        for (int kb = 0; kb < 8; kb++) {
#pragma unroll
            for (int fn = 0; fn < 8; fn++) {
                unsigned b[2];
                b[0] = f2tf(sK[(fn * 8 + gid) * SKSTR + kb * 8 + tig]);
                b[1] = f2tf(sK[(fn * 8 + gid) * SKSTR + kb * 8 + tig + 4]);
                mma8(sc[fn], qa[kb], b);
            }
        }
        // mask
#pragma unroll
        for (int fn = 0; fn < 8; fn++) {
            int g0 = kt * 64 + fn * 8 + 2 * tig;
            int g1 = g0 + 1;
            sc[fn][0] = (g0 > prow0 - 1024 && g0 <= prow0) ? sc[fn][0] : -1e30f;
            sc[fn][1] = (g1 > prow0 - 1024 && g1 <= prow0) ? sc[fn][1] : -1e30f;
            sc[fn][2] = (g0 > prow1 - 1024 && g0 <= prow1) ? sc[fn][2] : -1e30f;
            sc[fn][3] = (g1 > prow1 - 1024 && g1 <= prow1) ? sc[fn][3] : -1e30f;
        }
        // online softmax (rows gid, gid+8 per warp; reduce over quad = tig lanes)
        float t0 = -1e30f, t1 = -1e30f;
#pragma unroll
        for (int fn = 0; fn < 8; fn++) {
            t0 = fmaxf(t0, fmaxf(sc[fn][0], sc[fn][1]));
            t1 = fmaxf(t1, fmaxf(sc[fn][2], sc[fn][3]));
        }
#pragma unroll
        for (int off = 1; off < 4; off <<= 1) {
            t0 = fmaxf(t0, __shfl_xor_sync(0xffffffffu, t0, off));
            t1 = fmaxf(t1, __shfl_xor_sync(0xffffffffu, t1, off));
        }
        float mn0 = fmaxf(mrow0, t0), mn1 = fmaxf(mrow1, t1);
        float al0 = expf(mrow0 - mn0), al1 = expf(mrow1 - mn1);
        float mc0 = fmaxf(mn0, -1e20f), mc1 = fmaxf(mn1, -1e20f);
        float rs0 = 0.0f, rs1 = 0.0f;
#pragma unroll
        for (int fn = 0; fn < 8; fn++) {
            sc[fn][0] = expf(sc[fn][0] - mc0);
            sc[fn][1] = expf(sc[fn][1] - mc0);
            sc[fn][2] = expf(sc[fn][2] - mc1);
            sc[fn][3] = expf(sc[fn][3] - mc1);
            rs0 += sc[fn][0] + sc[fn][1];
            rs1 += sc[fn][2] + sc[fn][3];
        }
#pragma unroll
        for (int off = 1; off < 4; off <<= 1) {
            rs0 += __shfl_xor_sync(0xffffffffu, rs0, off);
            rs1 += __shfl_xor_sync(0xffffffffu, rs1, off);
        }
        lsum0 = lsum0 * al0 + rs0;
        lsum1 = lsum1 * al1 + rs1;
        mrow0 = mn0; mrow1 = mn1;
#pragma unroll
        for (int fn = 0; fn < 8; fn++) {
            o[fn][0] *= al0; o[fn][1] *= al0;
            o[fn][2] *= al1; o[fn][3] *= al1;
        }
        // write P to warp-private smem rows, then PV mma
        const int rp = warp * 16 + gid;
#pragma unroll
        for (int fn = 0; fn < 8; fn++) {
            sQP[rp * SQSTR + fn * 8 + 2 * tig]       = sc[fn][0];
            sQP[rp * SQSTR + fn * 8 + 2 * tig + 1]   = sc[fn][1];
            sQP[(rp + 8) * SQSTR + fn * 8 + 2 * tig]     = sc[fn][2];
            sQP[(rp + 8) * SQSTR + fn * 8 + 2 * tig + 1] = sc[fn][3];
        }
        __syncwarp();
#pragma unroll
        for (int kb = 0; kb < 8; kb++) {
            unsigned pa[4];
            pa[0] = f2tf(sQP[rp * SQSTR + kb * 8 + tig]);
            pa[1] = f2tf(sQP[(rp + 8) * SQSTR + kb * 8 + tig]);
            pa[2] = f2tf(sQP[rp * SQSTR + kb * 8 + tig + 4]);
            pa[3] = f2tf(sQP[(rp + 8) * SQSTR + kb * 8 + tig + 4]);
#pragma unroll
            for (int fn = 0; fn < 8; fn++) {
                unsigned b[2];
                b[0] = f2tf(sV[(kb * 8 + tig) * SVSTR + fn * 8 + gid]);
                b[1] = f2tf(sV[(kb * 8 + tig + 4) * SVSTR + fn * 8 + gid]);
                mma8(o[fn], pa, b);
            }
        }
        __syncwarp();
    }

    float inv0 = 1.0f / lsum0, inv1 = 1.0f / lsum1;
#pragma unroll
    for (int fn = 0; fn < 8; fn++) {
        int cc = h * HDIM + fn * 8 + 2 * tig;
        g_ao[(long)prow0 * DIM + cc]     = o[fn][0] * inv0;
        g_ao[(long)prow0 * DIM + cc + 1] = o[fn][1] * inv0;
        g_ao[(long)prow1 * DIM + cc]     = o[fn][2] * inv1;
        g_ao[(long)prow1 * DIM + cc + 1] = o[fn][3] * inv1;
    }
}

// TTT rmsnorm + add into g_ao
__global__ __launch_bounds__(256) void k_comb(const float* __restrict__ tnw)
{
    __shared__ float s_red[256];
    int s = blockIdx.x, t = threadIdx.x;
    float v[4], r[4];
#pragma unroll
    for (int i = 0; i < 4; i++) v[i] = g_ttt[(long)s * DIM + t + 256 * i];
#pragma unroll
    for (int i = 0; i < 4; i++) {
        float tot = block_reduce256(v[i] * v[i], s_red);
        r[i] = rsqrtf(tot / 256.0f + 1e-5f);
    }
    float w = tnw[t];
#pragma unroll
    for (int i = 0; i < 4; i++) g_ao[(long)s * DIM + t + 256 * i] += v[i] * r[i] * w;
}

__global__ __launch_bounds__(256) void k_gemm_out(const float* __restrict__ Wo,
                                                 float* __restrict__ out)
{
    gemm_tf32(g_ao, Wo, out, blockIdx.y * 128, blockIdx.x * 64,
              DIM, DIM, DIM, DIM, false, true, false);
}

// ------------------------- launch -------------------------
extern "C" void kernel_launch(void* const* d_in, const int* in_sizes, int n_in,
                              void* d_out, int out_size)
{
    const float* x    = (const float*)d_in[0];
    const float* Wqkv = (const float*)d_in[1];
    const float* qnw  = (const float*)d_in[2];
    const float* knw  = (const float*)d_in[3];
    const float* Wo   = (const float*)d_in[4];
    const float* w0   = (const float*)d_in[5];
    const float* w1   = (const float*)d_in[6];
    const float* w2   = (const float*)d_in[7];
    const float* Wlr  = (const float*)d_in[8];
    const float* blr  = (const float*)d_in[9];
    const float* qks  = (const float*)d_in[10];
    const float* qko  = (const float*)d_in[11];
    const float* tnw  = (const float*)d_in[12];
    float* out = (float*)d_out;

    cudaFuncSetAttribute(k_attn, cudaFuncAttributeMaxDynamicSharedMemorySize, ATTN_SMEM);

    k_initW<<<1024, 256>>>(w0, w1, w2);
    k_gemm_qkv<<<dim3(48, 32), 256>>>(x, Wqkv);
    k_lr<<<4096, 128>>>(x, Wlr, blr);
    k_post<<<4096, 256>>>(qnw, knw, qks, qko);

    for (int c = 0; c < NCH; c++) {
        k_ttt1<<<dim3(4, 8, 20), 256>>>(c);
        k_ttt2<<<4096, 256>>>(c);
        k_ttt3<<<dim3(4, 8, 4), 256>>>(c);
        k_ttt4<<<dim3(4, 2, 12), 256>>>(c);
    }

    k_attn<<<dim3(32, NHEAD), 256, ATTN_SMEM>>>();
    k_comb<<<4096, 256>>>(tnw);
    k_gemm_out<<<dim3(16, 32), 256>>>(Wo, out);
}

// round 3
// speedup vs baseline: 2.5646x; 1.3544x over previous
#include <cuda_runtime.h>
#include <math.h>

#define SEQ   4096
#define DIM   1024
#define NHEAD 16
#define HDIM  64
#define FHN   4
#define FDIM  256
#define CSZ   1024
#define NCH   4
#define BASE_LR_INV -6.90725517f

// ------------------------- scratch (static device globals) -------------------------
__device__ float g_qkv[SEQ * 3 * DIM];
__device__ float g_qr[SEQ * DIM];
__device__ float g_kr[SEQ * DIM];
__device__ float g_fq[SEQ * DIM];
__device__ float g_fk[SEQ * DIM];
__device__ float g_fv[SEQ * DIM];
__device__ float g_lrbuf[SEQ * 12];
__device__ float g_ttt[SEQ * DIM];
__device__ float g_ao[SEQ * DIM];
__device__ float g_W0[FHN * FDIM * FDIM];
__device__ float g_W1[FHN * FDIM * FDIM];
__device__ float g_W2[FHN * FDIM * FDIM];
__device__ float g_gk[FHN * CSZ * FDIM];
__device__ float g_hk[FHN * CSZ * FDIM];
__device__ float g_qg[FHN * CSZ * FDIM];
__device__ float g_qm[FHN * CSZ * FDIM];
__device__ float g_dh[FHN * CSZ * FDIM];
__device__ float g_hq[FHN * CSZ * FDIM];
__device__ float g_hid[FHN * CSZ * FDIM];
__device__ float g_dgk[FHN * CSZ * FDIM];
__device__ float g_dhk[FHN * CSZ * FDIM];
__device__ float g_vl1[FHN * CSZ * FDIM];

// ------------------------- tf32 mma primitives -------------------------
__device__ __forceinline__ unsigned f2tf(float f)
{
    unsigned u;
    asm("cvt.rna.tf32.f32 %0, %1;" : "=r"(u) : "f"(f));
    return u;
}

__device__ __forceinline__ void mma8(float* c, const unsigned* a, const unsigned* b)
{
    asm volatile(
        "mma.sync.aligned.m16n8k8.row.col.f32.tf32.tf32.f32 "
        "{%0,%1,%2,%3},{%4,%5,%6,%7},{%8,%9},{%0,%1,%2,%3};"
        : "+f"(c[0]), "+f"(c[1]), "+f"(c[2]), "+f"(c[3])
        : "r"(a[0]), "r"(a[1]), "r"(a[2]), "r"(a[3]), "r"(b[0]), "r"(b[1]));
}

// ------------------------- tf32 GEMM v2: CTA 128x128, warp 64x32 -------------------
// smem holds pre-converted tf32. Double-buffered, register prefetch, 1 sync/iter.
// !transA: A[M,K] lda ; transA: A[K,M] lda
// transB:  B[N,K] ldb ; !transB: B[K,N] ldb
// mode: 0 = store, 1 = +=, 2 = atomicAdd
#define SSTR 136

__device__ __forceinline__ void gemm128(
    const float* __restrict__ A, const float* __restrict__ B, float* __restrict__ C,
    int m0, int n0, int K, int lda, int ldb, int ldc,
    bool transA, bool transB, int mode)
{
    __shared__ unsigned As[2][16][SSTR];
    __shared__ unsigned Bs[2][16][SSTR];
    const int tid = threadIdx.x;
    const int lane = tid & 31, warp = tid >> 5;
    const int wm = warp >> 2, wn = warp & 3;      // 2 x 4 warps
    const int gid = lane >> 2, tig = lane & 3;

    float acc[4][4][4];
#pragma unroll
    for (int i = 0; i < 4; i++)
#pragma unroll
        for (int j = 0; j < 4; j++)
#pragma unroll
            for (int l = 0; l < 4; l++) acc[i][j][l] = 0.0f;

    float4 ar[2], br[2];

    // ---- prefetch helpers (LDG only) ----
    auto fetchA = [&](int k0) {
#pragma unroll
        for (int s = 0; s < 2; s++) {
            int lin = tid + 256 * s;
            if (!transA) {
                int m = lin >> 2, kq = (lin & 3) * 4;
                ar[s] = *(const float4*)(A + (long)(m0 + m) * lda + (k0 + kq));
            } else {
                int k = lin >> 5, m4 = (lin & 31) * 4;
                ar[s] = *(const float4*)(A + (long)(k0 + k) * lda + (m0 + m4));
            }
        }
    };
    auto fetchB = [&](int k0) {
#pragma unroll
        for (int s = 0; s < 2; s++) {
            int lin = tid + 256 * s;
            if (transB) {
                int n = lin >> 2, kq = (lin & 3) * 4;
                br[s] = *(const float4*)(B + (long)(n0 + n) * ldb + (k0 + kq));
            } else {
                int k = lin >> 5, n4 = (lin & 31) * 4;
                br[s] = *(const float4*)(B + (long)(k0 + k) * ldb + (n0 + n4));
            }
        }
    };
    auto storeA = [&](int buf) {
#pragma unroll
        for (int s = 0; s < 2; s++) {
            int lin = tid + 256 * s;
            if (!transA) {
                int m = lin >> 2, kq = (lin & 3) * 4;
                As[buf][kq + 0][m] = f2tf(ar[s].x);
                As[buf][kq + 1][m] = f2tf(ar[s].y);
                As[buf][kq + 2][m] = f2tf(ar[s].z);
                As[buf][kq + 3][m] = f2tf(ar[s].w);
            } else {
                int k = lin >> 5, m4 = (lin & 31) * 4;
                uint4 u = {f2tf(ar[s].x), f2tf(ar[s].y), f2tf(ar[s].z), f2tf(ar[s].w)};
                *(uint4*)&As[buf][k][m4] = u;
            }
        }
    };
    auto storeB = [&](int buf) {
#pragma unroll
        for (int s = 0; s < 2; s++) {
            int lin = tid + 256 * s;
            if (transB) {
                int n = lin >> 2, kq = (lin & 3) * 4;
                Bs[buf][kq + 0][n] = f2tf(br[s].x);
                Bs[buf][kq + 1][n] = f2tf(br[s].y);
                Bs[buf][kq + 2][n] = f2tf(br[s].z);
                Bs[buf][kq + 3][n] = f2tf(br[s].w);
            } else {
                int k = lin >> 5, n4 = (lin & 31) * 4;
                uint4 u = {f2tf(br[s].x), f2tf(br[s].y), f2tf(br[s].z), f2tf(br[s].w)};
                *(uint4*)&Bs[buf][k][n4] = u;
            }
        }
    };

    const int nk = K >> 4;
    fetchA(0); fetchB(0);
    storeA(0); storeB(0);
    __syncthreads();

    for (int t = 0; t < nk; t++) {
        const int cur = t & 1;
        if (t + 1 < nk) { fetchA((t + 1) << 4); fetchB((t + 1) << 4); }
#pragma unroll
        for (int kh = 0; kh < 16; kh += 8) {
            unsigned a[4][4], b[4][2];
#pragma unroll
            for (int fm = 0; fm < 4; fm++) {
                int mb = wm * 64 + fm * 16;
                a[fm][0] = As[cur][kh + tig][mb + gid];
                a[fm][1] = As[cur][kh + tig][mb + gid + 8];
                a[fm][2] = As[cur][kh + tig + 4][mb + gid];
                a[fm][3] = As[cur][kh + tig + 4][mb + gid + 8];
            }
#pragma unroll
            for (int fn = 0; fn < 4; fn++) {
                int nb = wn * 32 + fn * 8;
                b[fn][0] = Bs[cur][kh + tig][nb + gid];
                b[fn][1] = Bs[cur][kh + tig + 4][nb + gid];
            }
#pragma unroll
            for (int fm = 0; fm < 4; fm++)
#pragma unroll
                for (int fn = 0; fn < 4; fn++) mma8(acc[fm][fn], a[fm], b[fn]);
        }
        if (t + 1 < nk) { storeA(cur ^ 1); storeB(cur ^ 1); }
        __syncthreads();
    }

#pragma unroll
    for (int fm = 0; fm < 4; fm++) {
        int r0 = m0 + wm * 64 + fm * 16 + gid;
#pragma unroll
        for (int fn = 0; fn < 4; fn++) {
            int cc = n0 + wn * 32 + fn * 8 + 2 * tig;
            float* p0 = C + (long)r0 * ldc + cc;
            float* p1 = C + (long)(r0 + 8) * ldc + cc;
            if (mode == 0) {
                p0[0] = acc[fm][fn][0]; p0[1] = acc[fm][fn][1];
                p1[0] = acc[fm][fn][2]; p1[1] = acc[fm][fn][3];
            } else if (mode == 1) {
                p0[0] += acc[fm][fn][0]; p0[1] += acc[fm][fn][1];
                p1[0] += acc[fm][fn][2]; p1[1] += acc[fm][fn][3];
            } else {
                atomicAdd(p0, acc[fm][fn][0]); atomicAdd(p0 + 1, acc[fm][fn][1]);
                atomicAdd(p1, acc[fm][fn][2]); atomicAdd(p1 + 1, acc[fm][fn][3]);
            }
        }
    }
}

// ------------------------- helpers -------------------------
__device__ __forceinline__ float sigmoidf_(float x) { return 1.0f / (1.0f + expf(-x)); }

__device__ __forceinline__ float warp_sum(float v)
{
#pragma unroll
    for (int o = 16; o > 0; o >>= 1) v += __shfl_xor_sync(0xffffffffu, v, o);
    return v;
}

// ------------------------- kernels -------------------------
__global__ void k_initW(const float* __restrict__ w0, const float* __restrict__ w1,
                        const float* __restrict__ w2)
{
    int i = blockIdx.x * blockDim.x + threadIdx.x;
    if (i < FHN * FDIM * FDIM) { g_W0[i] = w0[i]; g_W1[i] = w1[i]; g_W2[i] = w2[i]; }
}

__global__ __launch_bounds__(256) void k_gemm_qkv(const float* __restrict__ x,
                                                  const float* __restrict__ Wqkv)
{
    gemm128(x, Wqkv, g_qkv, blockIdx.y * 128, blockIdx.x * 128,
            DIM, DIM, DIM, 3 * DIM, false, true, 0);
}

__global__ __launch_bounds__(128) void k_lr(const float* __restrict__ x,
                                            const float* __restrict__ Wlr,
                                            const float* __restrict__ blr)
{
    __shared__ float sx[DIM];
    int s = blockIdx.x;
    for (int i = threadIdx.x; i < DIM; i += 128) sx[i] = x[(long)s * DIM + i];
    __syncthreads();
    int w = threadIdx.x >> 5, lane = threadIdx.x & 31;
    for (int j = w; j < 12; j += 4) {
        float sum = 0.0f;
        for (int d = lane; d < DIM; d += 32) sum += sx[d] * Wlr[(long)j * DIM + d];
        sum = warp_sum(sum);
        if (lane == 0) {
            float v = sum + blr[j] + BASE_LR_INV;
            g_lrbuf[s * 12 + j] = (v > 20.0f) ? v : log1pf(expf(v));
        }
    }
}

// RMSNorm(q,k) + fast-weight inputs + fv + RoPE(q,k); shuffle-based reductions
__global__ __launch_bounds__(256) void k_post(const float* __restrict__ qnw,
                                              const float* __restrict__ knw,
                                              const float* __restrict__ qks,
                                              const float* __restrict__ qko)
{
    __shared__ float s_q[DIM];
    __shared__ float s_k[DIM];
    __shared__ float s_part[8][12];
    __shared__ float s_fin[12];
    __shared__ float s_cs[32], s_sn[32];

    int s = blockIdx.x, t = threadIdx.x;
    int lane = t & 31, w = t >> 5;
    const float* qrow = g_qkv + (long)s * 3072;
    const float* krow = qrow + DIM;
    const float* vrow = qrow + 2 * DIM;

    if (t < 32) {
        double inv = exp(-((double)(2 * t) / 64.0) * log(500000.0));
        double a = (double)s * inv;
        const double tw = 6.283185307179586476925286766559;
        a -= floor(a / tw) * tw;
        s_cs[t] = (float)cos(a);
        s_sn[t] = (float)sin(a);
    }

    float qv[4], kv[4], vv[4];
    float sq = 0.0f, sk = 0.0f;
#pragma unroll
    for (int i = 0; i < 4; i++) {
        int d = t + 256 * i;
        qv[i] = qrow[d]; kv[i] = krow[d]; vv[i] = vrow[d];
        sq += qv[i] * qv[i]; sk += kv[i] * kv[i];
    }
    sq = warp_sum(sq); sk = warp_sum(sk);
    if (lane == 0) { s_part[w][0] = sq; s_part[w][1] = sk; }
    __syncthreads();
    if (t < 2) {
        float a = 0.0f;
#pragma unroll
        for (int i = 0; i < 8; i++) a += s_part[i][t];
        s_fin[t] = a;
    }
    __syncthreads();
    float rq = rsqrtf(s_fin[0] / 1024.0f + 1e-5f);
    float rk = rsqrtf(s_fin[1] / 1024.0f + 1e-5f);

    float fqv[4], fkv[4];
    float p8[8];
#pragma unroll
    for (int i = 0; i < 4; i++) {
        int d = t + 256 * i;
        float qn = qv[i] * rq * qnw[d];
        float kn = kv[i] * rk * knw[d];
        s_q[d] = qn; s_k[d] = kn;
        fqv[i] = qn * sigmoidf_(qn) * qks[2 * d + 0] + qko[2 * d + 0];
        fkv[i] = kn * sigmoidf_(kn) * qks[2 * d + 1] + qko[2 * d + 1];
        g_fv[(long)s * DIM + d] = vv[i] * sigmoidf_(vv[i]);
        p8[i] = fqv[i] * fqv[i];
        p8[4 + i] = fkv[i] * fkv[i];
    }
#pragma unroll
    for (int j = 0; j < 8; j++) p8[j] = warp_sum(p8[j]);
    if (lane == 0)
#pragma unroll
        for (int j = 0; j < 8; j++) s_part[w][j] = p8[j];
    __syncthreads();
    if (t < 8) {
        float a = 0.0f;
#pragma unroll
        for (int i = 0; i < 8; i++) a += s_part[i][t];
        s_fin[t] = a;
    }
    __syncthreads();
#pragma unroll
    for (int i = 0; i < 4; i++) {
        int d = t + 256 * i;
        g_fq[(long)s * DIM + d] = fqv[i] * rsqrtf(s_fin[i] + 1e-6f);
        g_fk[(long)s * DIM + d] = fkv[i] * rsqrtf(s_fin[4 + i] + 1e-6f);
    }
#pragma unroll
    for (int i = 0; i < 4; i++) {
        int d = t + 256 * i;
        int r = d & 63, ip = r & 31;
        float c = s_cs[ip], sn = s_sn[ip];
        float x1q = s_q[d], xpq = s_q[d ^ 32];
        float x1k = s_k[d], xpk = s_k[d ^ 32];
        g_qr[(long)s * DIM + d] = (r < 32) ? x1q * c - xpq * sn : x1q * c + xpq * sn;
        g_kr[(long)s * DIM + d] = (r < 32) ? x1k * c - xpk * sn : x1k * c + xpk * sn;
    }
}

// TTT stage 1: gk,hk,qg,qm (A@W^T) and dh (A@W1)
__global__ __launch_bounds__(256) void k_ttt1(int c)
{
    int z = blockIdx.z;
    int h = z / 5, op = z - h * 5;
    long choff = (long)c * CSZ * DIM + h * FDIM;
    const float* A; const float* B; float* Cp; bool tb = true;
    switch (op) {
        case 0: A = g_fk + choff; B = g_W0 + h * FDIM * FDIM; Cp = g_gk + (long)h * CSZ * FDIM; break;
        case 1: A = g_fk + choff; B = g_W2 + h * FDIM * FDIM; Cp = g_hk + (long)h * CSZ * FDIM; break;
        case 2: A = g_fq + choff; B = g_W0 + h * FDIM * FDIM; Cp = g_qg + (long)h * CSZ * FDIM; break;
        case 3: A = g_fq + choff; B = g_W2 + h * FDIM * FDIM; Cp = g_qm + (long)h * CSZ * FDIM; break;
        default: A = g_fv + choff; B = g_W1 + h * FDIM * FDIM; Cp = g_dh + (long)h * CSZ * FDIM; tb = false; break;
    }
    gemm128(A, B, Cp, blockIdx.y * 128, blockIdx.x * 128, FDIM, DIM, FDIM, FDIM, false, tb, 0);
}

// TTT stage 2: elementwise activations / lr scaling
__global__ __launch_bounds__(256) void k_ttt2(int c)
{
    long idx = (long)blockIdx.x * 256 + threadIdx.x;
    int h = (int)(idx >> 18);
    int rem = (int)(idx & 262143);
    int t = rem >> 8;
    int e = rem & 255;
    int sg = c * CSZ + t;
    float l0 = g_lrbuf[sg * 12 + h];
    float l1 = g_lrbuf[sg * 12 + 4 + h];
    float l2 = g_lrbuf[sg * 12 + 8 + h];
    float gk = g_gk[idx], hk = g_hk[idx], dh = g_dh[idx];
    float qg = g_qg[idx], qm = g_qm[idx];
    float sgm = sigmoidf_(gk);
    float sil = gk * sgm;
    g_hq[idx]  = qg * sigmoidf_(qg) * qm;
    g_hid[idx] = sil * hk;
    float dsil = sgm * (1.0f + gk * (1.0f - sgm));
    g_dgk[idx] = dh * hk * dsil * l0;
    g_dhk[idx] = dh * sil * l2;
    g_vl1[idx] = g_fv[(long)sg * DIM + h * FDIM + e] * l1;
}

// TTT stage 3: oi = hq @ W1^T
__global__ __launch_bounds__(256) void k_ttt3(int c)
{
    int h = blockIdx.z;
    gemm128(g_hq + (long)h * CSZ * FDIM, g_W1 + h * FDIM * FDIM,
            g_ttt + (long)c * CSZ * DIM + h * FDIM,
            blockIdx.y * 128, blockIdx.x * 128, FDIM, FDIM, FDIM, DIM, false, true, 0);
}

// TTT stage 4: rank-CSZ weight updates, split-K 4x with atomic accumulate
__global__ __launch_bounds__(256) void k_ttt4(int c)
{
    int z = blockIdx.z;
    int h = z / 12;
    int r = z - h * 12;
    int op = r >> 2, sl = r & 3;
    long koff = (long)c * CSZ * DIM + h * FDIM;
    const float* A; const float* B; float* Cp; int lda, ldb;
    switch (op) {
        case 0: A = g_vl1 + (long)h * CSZ * FDIM; B = g_hid + (long)h * CSZ * FDIM;
                Cp = g_W1 + h * FDIM * FDIM; lda = FDIM; ldb = FDIM; break;
        case 1: A = g_dgk + (long)h * CSZ * FDIM; B = g_fk + koff;
                Cp = g_W0 + h * FDIM * FDIM; lda = FDIM; ldb = DIM; break;
        default: A = g_dhk + (long)h * CSZ * FDIM; B = g_fk + koff;
                Cp = g_W2 + h * FDIM * FDIM; lda = FDIM; ldb = DIM; break;
    }
    A += (long)sl * 256 * lda;
    B += (long)sl * 256 * ldb;
    gemm128(A, B, Cp, blockIdx.y * 128, blockIdx.x * 128, 256, lda, ldb, FDIM, true, false, 2);
}

// ------------------------- tf32 flash attention, 128-query tiles -------------------------
#define SQSTR 68
#define SKSTR 68
#define SVSTR 72
#define ATTN_SMEM ((128 * SQSTR + 64 * SKSTR + 64 * SVSTR) * 4)

__global__ __launch_bounds__(256) void k_attn()
{
    extern __shared__ float sm[];
    float* sQP = sm;                                   // [128][SQSTR] Q then P (float)
    unsigned* sK = (unsigned*)(sm + 128 * SQSTR);      // [64][SKSTR] pre-converted tf32
    unsigned* sV = (unsigned*)(sm + 128 * SQSTR + 64 * SKSTR);  // [64][SVSTR]

    const int h = blockIdx.y, qt = blockIdx.x;
    const int p0 = qt * 128;
    const int tid = threadIdx.x;
    const int lane = tid & 31, warp = tid >> 5;
    const int gid = lane >> 2, tig = lane & 3;

#pragma unroll
    for (int s = 0; s < 8; s++) {
        int lin = tid + 256 * s;
        int r = lin >> 4, c4 = (lin & 15) * 4;
        *(float4*)&sQP[r * SQSTR + c4] =
            *(const float4*)&g_qr[(long)(p0 + r) * DIM + h * HDIM + c4];
    }
    __syncthreads();

    const int rq = warp * 16 + gid;
    unsigned qa[8][4];
#pragma unroll
    for (int kb = 0; kb < 8; kb++) {
        qa[kb][0] = f2tf(0.125f * sQP[rq * SQSTR + kb * 8 + tig]);
        qa[kb][1] = f2tf(0.125f * sQP[(rq + 8) * SQSTR + kb * 8 + tig]);
        qa[kb][2] = f2tf(0.125f * sQP[rq * SQSTR + kb * 8 + tig + 4]);
        qa[kb][3] = f2tf(0.125f * sQP[(rq + 8) * SQSTR + kb * 8 + tig + 4]);
    }

    float o[8][4];
#pragma unroll
    for (int fn = 0; fn < 8; fn++)
#pragma unroll
        for (int j = 0; j < 4; j++) o[fn][j] = 0.0f;
    float mrow0 = -1e30f, mrow1 = -1e30f, lsum0 = 0.0f, lsum1 = 0.0f;

    const int ktlo = (qt >= 8) ? 2 * qt - 16 : 0;
    const int kthi = 2 * qt + 1;
    const int prow0 = p0 + warp * 16 + gid;
    const int prow1 = prow0 + 8;

    for (int kt = ktlo; kt <= kthi; kt++) {
        __syncthreads();
#pragma unroll
        for (int s = 0; s < 4; s++) {
            int lin = tid + 256 * s;
            int r = lin >> 4, c4 = (lin & 15) * 4;
            float4 kv = *(const float4*)&g_kr[(long)(kt * 64 + r) * DIM + h * HDIM + c4];
            uint4 ku = {f2tf(kv.x), f2tf(kv.y), f2tf(kv.z), f2tf(kv.w)};
            *(uint4*)&sK[r * SKSTR + c4] = ku;
            float4 vv = *(const float4*)&g_qkv[(long)(kt * 64 + r) * 3072 + 2048 + h * HDIM + c4];
            uint4 vu = {f2tf(vv.x), f2tf(vv.y), f2tf(vv.z), f2tf(vv.w)};
            *(uint4*)&sV[r * SVSTR + c4] = vu;
        }
        __syncthreads();

        float sc[8][4];
#pragma unroll
        for (int fn = 0; fn < 8; fn++)
#pragma unroll
            for (int j = 0; j < 4; j++) sc[fn][j] = 0.0f;

#pragma unroll
        for (int kb = 0; kb < 8; kb++) {
#pragma unroll
            for (int fn = 0; fn < 8; fn++) {
                unsigned b[2];
                b[0] = sK[(fn * 8 + gid) * SKSTR + kb * 8 + tig];
                b[1] = sK[(fn * 8 + gid) * SKSTR + kb * 8 + tig + 4];
                mma8(sc[fn], qa[kb], b);
            }
        }
#pragma unroll
        for (int fn = 0; fn < 8; fn++) {
            int g0 = kt * 64 + fn * 8 + 2 * tig;
            int g1 = g0 + 1;
            sc[fn][0] = (g0 > prow0 - 1024 && g0 <= prow0) ? sc[fn][0] : -1e30f;
            sc[fn][1] = (g1 > prow0 - 1024 && g1 <= prow0) ? sc[fn][1] : -1e30f;
            sc[fn][2] = (g0 > prow1 - 1024 && g0 <= prow1) ? sc[fn][2] : -1e30f;
            sc[fn][3] = (g1 > prow1 - 1024 && g1 <= prow1) ? sc[fn][3] : -1e30f;
        }
        float t0 = -1e30f, t1 = -1e30f;
#pragma unroll
        for (int fn = 0; fn < 8; fn++) {
            t0 = fmaxf(t0, fmaxf(sc[fn][0], sc[fn][1]));
            t1 = fmaxf(t1, fmaxf(sc[fn][2], sc[fn][3]));
        }
#pragma unroll
        for (int off = 1; off < 4; off <<= 1) {
            t0 = fmaxf(t0, __shfl_xor_sync(0xffffffffu, t0, off));
            t1 = fmaxf(t1, __shfl_xor_sync(0xffffffffu, t1, off));
        }
        float mn0 = fmaxf(mrow0, t0), mn1 = fmaxf(mrow1, t1);
        float al0 = expf(mrow0 - mn0), al1 = expf(mrow1 - mn1);
        float mc0 = fmaxf(mn0, -1e20f), mc1 = fmaxf(mn1, -1e20f);
        float rs0 = 0.0f, rs1 = 0.0f;
#pragma unroll
        for (int fn = 0; fn < 8; fn++) {
            sc[fn][0] = expf(sc[fn][0] - mc0);
            sc[fn][1] = expf(sc[fn][1] - mc0);
            sc[fn][2] = expf(sc[fn][2] - mc1);
            sc[fn][3] = expf(sc[fn][3] - mc1);
            rs0 += sc[fn][0] + sc[fn][1];
            rs1 += sc[fn][2] + sc[fn][3];
        }
#pragma unroll
        for (int off = 1; off < 4; off <<= 1) {
            rs0 += __shfl_xor_sync(0xffffffffu, rs0, off);
            rs1 += __shfl_xor_sync(0xffffffffu, rs1, off);
        }
        lsum0 = lsum0 * al0 + rs0;
        lsum1 = lsum1 * al1 + rs1;
        mrow0 = mn0; mrow1 = mn1;
#pragma unroll
        for (int fn = 0; fn < 8; fn++) {
            o[fn][0] *= al0; o[fn][1] *= al0;
            o[fn][2] *= al1; o[fn][3] *= al1;
        }
        const int rp = warp * 16 + gid;
#pragma unroll
        for (int fn = 0; fn < 8; fn++) {
            sQP[rp * SQSTR + fn * 8 + 2 * tig]           = sc[fn][0];
            sQP[rp * SQSTR + fn * 8 + 2 * tig + 1]       = sc[fn][1];
            sQP[(rp + 8) * SQSTR + fn * 8 + 2 * tig]     = sc[fn][2];
            sQP[(rp + 8) * SQSTR + fn * 8 + 2 * tig + 1] = sc[fn][3];
        }
        __syncwarp();
#pragma unroll
        for (int kb = 0; kb < 8; kb++) {
            unsigned pa[4];
            pa[0] = f2tf(sQP[rp * SQSTR + kb * 8 + tig]);
            pa[1] = f2tf(sQP[(rp + 8) * SQSTR + kb * 8 + tig]);
            pa[2] = f2tf(sQP[rp * SQSTR + kb * 8 + tig + 4]);
            pa[3] = f2tf(sQP[(rp + 8) * SQSTR + kb * 8 + tig + 4]);
#pragma unroll
            for (int fn = 0; fn < 8; fn++) {
                unsigned b[2];
                b[0] = sV[(kb * 8 + tig) * SVSTR + fn * 8 + gid];
                b[1] = sV[(kb * 8 + tig + 4) * SVSTR + fn * 8 + gid];
                mma8(o[fn], pa, b);
            }
        }
        __syncwarp();
    }

    float inv0 = 1.0f / lsum0, inv1 = 1.0f / lsum1;
#pragma unroll
    for (int fn = 0; fn < 8; fn++) {
        int cc = h * HDIM + fn * 8 + 2 * tig;
        g_ao[(long)prow0 * DIM + cc]     = o[fn][0] * inv0;
        g_ao[(long)prow0 * DIM + cc + 1] = o[fn][1] * inv0;
        g_ao[(long)prow1 * DIM + cc]     = o[fn][2] * inv1;
        g_ao[(long)prow1 * DIM + cc + 1] = o[fn][3] * inv1;
    }
}

// TTT rmsnorm + add into g_ao (shuffle reductions)
__global__ __launch_bounds__(256) void k_comb(const float* __restrict__ tnw)
{
    __shared__ float s_part[8][4];
    __shared__ float s_fin[4];
    int s = blockIdx.x, t = threadIdx.x;
    int lane = t & 31, w = t >> 5;
    float v[4], p4[4];
#pragma unroll
    for (int i = 0; i < 4; i++) {
        v[i] = g_ttt[(long)s * DIM + t + 256 * i];
        p4[i] = v[i] * v[i];
    }
#pragma unroll
    for (int j = 0; j < 4; j++) p4[j] = warp_sum(p4[j]);
    if (lane == 0)
#pragma unroll
        for (int j = 0; j < 4; j++) s_part[w][j] = p4[j];
    __syncthreads();
    if (t < 4) {
        float a = 0.0f;
#pragma unroll
        for (int i = 0; i < 8; i++) a += s_part[i][t];
        s_fin[t] = a;
    }
    __syncthreads();
    float wgt = tnw[t];
#pragma unroll
    for (int i = 0; i < 4; i++) {
        float r = rsqrtf(s_fin[i] / 256.0f + 1e-5f);
        g_ao[(long)s * DIM + t + 256 * i] += v[i] * r * wgt;
    }
}

__global__ __launch_bounds__(256) void k_gemm_out(const float* __restrict__ Wo,
                                                 float* __restrict__ out)
{
    gemm128(g_ao, Wo, out, blockIdx.y * 128, blockIdx.x * 128,
            DIM, DIM, DIM, DIM, false, true, 0);
}

// ------------------------- launch -------------------------
extern "C" void kernel_launch(void* const* d_in, const int* in_sizes, int n_in,
                              void* d_out, int out_size)
{
    const float* x    = (const float*)d_in[0];
    const float* Wqkv = (const float*)d_in[1];
    const float* qnw  = (const float*)d_in[2];
    const float* knw  = (const float*)d_in[3];
    const float* Wo   = (const float*)d_in[4];
    const float* w0   = (const float*)d_in[5];
    const float* w1   = (const float*)d_in[6];
    const float* w2   = (const float*)d_in[7];
    const float* Wlr  = (const float*)d_in[8];
    const float* blr  = (const float*)d_in[9];
    const float* qks  = (const float*)d_in[10];
    const float* qko  = (const float*)d_in[11];
    const float* tnw  = (const float*)d_in[12];
    float* out = (float*)d_out;

    cudaFuncSetAttribute(k_attn, cudaFuncAttributeMaxDynamicSharedMemorySize, ATTN_SMEM);

    k_initW<<<1024, 256>>>(w0, w1, w2);
    k_gemm_qkv<<<dim3(24, 32), 256>>>(x, Wqkv);
    k_lr<<<4096, 128>>>(x, Wlr, blr);
    k_post<<<4096, 256>>>(qnw, knw, qks, qko);

    for (int c = 0; c < NCH; c++) {
        k_ttt1<<<dim3(2, 8, 20), 256>>>(c);
        k_ttt2<<<4096, 256>>>(c);
        k_ttt3<<<dim3(2, 8, 4), 256>>>(c);
        k_ttt4<<<dim3(2, 2, 48), 256>>>(c);
    }

    k_attn<<<dim3(32, NHEAD), 256, ATTN_SMEM>>>();
    k_comb<<<4096, 256>>>(tnw);
    k_gemm_out<<<dim3(8, 32), 256>>>(Wo, out);
}